// round 3
// baseline (speedup 1.0000x reference)
#include <cuda_runtime.h>
#include <cstdint>

// Blocked Hadamard transform, BLOCK = 256 = 4^4.
// H = kron(H4,H4,H4,H4) * (1/16), H4 rows: [1,1,1,-1],[1,1,-1,1],[1,-1,1,1],[-1,1,1,1]
// out[i] = sum_j H[i,j] x[j] per 256-block == radix-4 butterflies along each
// base-4 digit (strides 1,4,16,64), final scale 1/16.
//
// Layout: thread owns 16 consecutive floats (digits j0,j1 local).
// 16 lanes = one 256-block; one warp = two blocks = 512 contiguous floats.
// Cross-lane stages (strides 16,64) via shfl_xor {1,2,3} / {4,8,12};
// sign pattern is lane-uniform: y = x + x^1 + x^2 - x^3.

__global__ void __launch_bounds__(256) hadamard256_kernel(
    const float* __restrict__ x, float* __restrict__ out)
{
    const unsigned warp_global = blockIdx.x * 8u + (threadIdx.x >> 5);
    const unsigned lane = threadIdx.x & 31u;
    const size_t base = (size_t)warp_global * 512u + (size_t)lane * 16u;

    float v[16];
    const float4* src = reinterpret_cast<const float4*>(x + base);
    float4 t0 = src[0];
    float4 t1 = src[1];
    float4 t2 = src[2];
    float4 t3 = src[3];
    v[0]=t0.x; v[1]=t0.y; v[2]=t0.z; v[3]=t0.w;
    v[4]=t1.x; v[5]=t1.y; v[6]=t1.z; v[7]=t1.w;
    v[8]=t2.x; v[9]=t2.y; v[10]=t2.z; v[11]=t2.w;
    v[12]=t3.x; v[13]=t3.y; v[14]=t3.z; v[15]=t3.w;

    // Stage 0: H4 over digit j0 (stride 1, local)
    #pragma unroll
    for (int g = 0; g < 4; g++) {
        float x0 = v[4*g+0], x1 = v[4*g+1], x2 = v[4*g+2], x3 = v[4*g+3];
        float s01 = x0 + x1, d01 = x0 - x1;
        float s23 = x2 + x3, d23 = x2 - x3;
        v[4*g+0] = s01 + d23;   //  x0+x1+x2-x3
        v[4*g+1] = s01 - d23;   //  x0+x1-x2+x3
        v[4*g+2] = d01 + s23;   //  x0-x1+x2+x3
        v[4*g+3] = s23 - d01;   // -x0+x1+x2+x3
    }

    // Stage 1: H4 over digit j1 (stride 4, local)
    #pragma unroll
    for (int g = 0; g < 4; g++) {
        float x0 = v[g+0], x1 = v[g+4], x2 = v[g+8], x3 = v[g+12];
        float s01 = x0 + x1, d01 = x0 - x1;
        float s23 = x2 + x3, d23 = x2 - x3;
        v[g+0]  = s01 + d23;
        v[g+4]  = s01 - d23;
        v[g+8]  = d01 + s23;
        v[g+12] = s23 - d01;
    }

    // Stage 2: H4 over digit p0 = lane bits [1:0] (stride 16, cross-lane)
    #pragma unroll
    for (int j = 0; j < 16; j++) {
        float a = __shfl_xor_sync(0xffffffffu, v[j], 1);
        float b = __shfl_xor_sync(0xffffffffu, v[j], 2);
        float c = __shfl_xor_sync(0xffffffffu, v[j], 3);
        v[j] = (v[j] + a) + (b - c);
    }

    // Stage 3: H4 over digit p1 = lane bits [3:2] (stride 64, cross-lane)
    // Fold the 1/sqrt(256) = 1/16 scale into the output.
    #pragma unroll
    for (int j = 0; j < 16; j++) {
        float a = __shfl_xor_sync(0xffffffffu, v[j], 4);
        float b = __shfl_xor_sync(0xffffffffu, v[j], 8);
        float c = __shfl_xor_sync(0xffffffffu, v[j], 12);
        v[j] = ((v[j] + a) + (b - c)) * 0.0625f;
    }

    float4* dst = reinterpret_cast<float4*>(out + base);
    dst[0] = make_float4(v[0],  v[1],  v[2],  v[3]);
    dst[1] = make_float4(v[4],  v[5],  v[6],  v[7]);
    dst[2] = make_float4(v[8],  v[9],  v[10], v[11]);
    dst[3] = make_float4(v[12], v[13], v[14], v[15]);
}

extern "C" void kernel_launch(void* const* d_in, const int* in_sizes, int n_in,
                              void* d_out, int out_size)
{
    const float* x = (const float*)d_in[0];
    float* out = (float*)d_out;

    // out_size = 2*4096*8192 = 67,108,864 floats.
    // One warp handles 512 floats; 8 warps (256 threads) per CTA -> 4096 floats/CTA.
    const long long n = (long long)out_size;
    const int cta_elems = 4096;
    const int grid = (int)(n / cta_elems);   // 16384, exact (8192 % 256 == 0)

    hadamard256_kernel<<<grid, 256>>>(x, out);
}

// round 4
// speedup vs baseline: 1.1609x; 1.1609x over previous
#include <cuda_runtime.h>
#include <cstdint>

// Blocked Hadamard transform, BLOCK = 256 = 4^4.
// H4 = ones(4) - 2*antidiag ; H = kron(H4 x4) / 16.
// Radix-4 butterflies along base-4 digits (strides 1,4,16,64), scale 1/16.
//
// Layout: thread owns 16 consecutive floats (digits j0,j1 local).
// 16 lanes = one 256-block; warp = two blocks = 512 contiguous floats.
// Cross-lane stages use the 2-shuffle identity:
//   y_l = x_l + x_{l^1} + x_{l^2} - x_{l^3}
//       = (x + shfl_xor(x,m)) + shfl_xor(x - shfl_xor(x,m), 2m)
// (m = 1 for the stride-16 digit, m = 4 for the stride-64 digit).

__global__ void __launch_bounds__(256) hadamard256_kernel(
    const float* __restrict__ x, float* __restrict__ out)
{
    const unsigned warp_global = blockIdx.x * 8u + (threadIdx.x >> 5);
    const unsigned lane = threadIdx.x & 31u;
    const size_t base = (size_t)warp_global * 512u + (size_t)lane * 16u;

    float v[16];
    const float4* src = reinterpret_cast<const float4*>(x + base);
    float4 t0 = src[0];
    float4 t1 = src[1];
    float4 t2 = src[2];
    float4 t3 = src[3];
    v[0]=t0.x; v[1]=t0.y; v[2]=t0.z; v[3]=t0.w;
    v[4]=t1.x; v[5]=t1.y; v[6]=t1.z; v[7]=t1.w;
    v[8]=t2.x; v[9]=t2.y; v[10]=t2.z; v[11]=t2.w;
    v[12]=t3.x; v[13]=t3.y; v[14]=t3.z; v[15]=t3.w;

    // Stage 0: H4 over digit j0 (stride 1, local)
    #pragma unroll
    for (int g = 0; g < 4; g++) {
        float x0 = v[4*g+0], x1 = v[4*g+1], x2 = v[4*g+2], x3 = v[4*g+3];
        float s01 = x0 + x1, d01 = x0 - x1;
        float s23 = x2 + x3, d23 = x2 - x3;
        v[4*g+0] = s01 + d23;   //  x0+x1+x2-x3
        v[4*g+1] = s01 - d23;   //  x0+x1-x2+x3
        v[4*g+2] = d01 + s23;   //  x0-x1+x2+x3
        v[4*g+3] = s23 - d01;   // -x0+x1+x2+x3
    }

    // Stage 1: H4 over digit j1 (stride 4, local)
    #pragma unroll
    for (int g = 0; g < 4; g++) {
        float x0 = v[g+0], x1 = v[g+4], x2 = v[g+8], x3 = v[g+12];
        float s01 = x0 + x1, d01 = x0 - x1;
        float s23 = x2 + x3, d23 = x2 - x3;
        v[g+0]  = s01 + d23;
        v[g+4]  = s01 - d23;
        v[g+8]  = d01 + s23;
        v[g+12] = s23 - d01;
    }

    // Stage 2: H4 over lane bits [1:0] (stride 16) — 2 shuffles per value
    #pragma unroll
    for (int j = 0; j < 16; j++) {
        float a  = __shfl_xor_sync(0xffffffffu, v[j], 1);
        float s  = v[j] + a;
        float d  = v[j] - a;
        float d2 = __shfl_xor_sync(0xffffffffu, d, 2);
        v[j] = s + d2;
    }

    // Stage 3: H4 over lane bits [3:2] (stride 64) — 2 shuffles per value.
    // Fold the 1/16 scale into the output.
    #pragma unroll
    for (int j = 0; j < 16; j++) {
        float a  = __shfl_xor_sync(0xffffffffu, v[j], 4);
        float s  = v[j] + a;
        float d  = v[j] - a;
        float d2 = __shfl_xor_sync(0xffffffffu, d, 8);
        v[j] = (s + d2) * 0.0625f;
    }

    float4* dst = reinterpret_cast<float4*>(out + base);
    dst[0] = make_float4(v[0],  v[1],  v[2],  v[3]);
    dst[1] = make_float4(v[4],  v[5],  v[6],  v[7]);
    dst[2] = make_float4(v[8],  v[9],  v[10], v[11]);
    dst[3] = make_float4(v[12], v[13], v[14], v[15]);
}

extern "C" void kernel_launch(void* const* d_in, const int* in_sizes, int n_in,
                              void* d_out, int out_size)
{
    const float* x = (const float*)d_in[0];
    float* out = (float*)d_out;

    // out_size = 2*4096*8192 = 67,108,864 floats.
    // One warp handles 512 floats; 8 warps (256 threads) per CTA -> 4096 floats/CTA.
    const long long n = (long long)out_size;
    const int cta_elems = 4096;
    const int grid = (int)(n / cta_elems);   // 16384, exact

    hadamard256_kernel<<<grid, 256>>>(x, out);
}

// round 5
// speedup vs baseline: 1.2306x; 1.0601x over previous
#include <cuda_runtime.h>
#include <cstdint>

// Blocked Hadamard transform, BLOCK = 256 = 4^4.
// H4 = ones(4) - 2*antidiag ; H = kron(H4 x4) / 16.
// Per-block index i = a + 16*b, a,b in [0,16). Stages over a have strides 1,4;
// stages over b have strides 16,64. All stages commute.
//
// Scheme: thread q loads v[b] = x[16b + q] (strided scalar loads, warp-coalesced),
// does the two b-digit H4 stages locally, transposes 16x16 through shared memory
// (stride-20 rows: conflict-free scalar STS + conflict-free LDS.128), does the
// two a-digit stages locally, and writes 16 consecutive floats via STG.128.
// No shuffles, one transpose, __syncwarp only.

__global__ void __launch_bounds__(256) hadamard256_kernel(
    const float* __restrict__ x, float* __restrict__ out)
{
    // Per warp: 2 blocks. Each block: 16 rows * stride 20 = 320 words, blockB at
    // +336 (336 % 32 == 16 -> bank offset 16 so both halves cover all 32 banks).
    __shared__ float sm[8 * 672];

    const unsigned warp_in_cta = threadIdx.x >> 5;
    const unsigned lane = threadIdx.x & 31u;
    const unsigned half = lane >> 4;        // which 256-block within the warp
    const unsigned q    = lane & 15u;       // owned a-digit before transpose

    const unsigned warp_global = blockIdx.x * 8u + warp_in_cta;
    const size_t gbase = (size_t)warp_global * 512u + (size_t)half * 256u;

    float* W = sm + warp_in_cta * 672u + half * 336u;

    // ---- Load: v[b] = x[gbase + 16*b + q]  (16 coalesced scalar loads) ----
    float v[16];
    const float* xp = x + gbase + q;
    #pragma unroll
    for (int b = 0; b < 16; b++)
        v[b] = xp[b * 16];

    // ---- Stage over b0 (block stride 16): H4 on (b, b^1-ish groups of 4) ----
    #pragma unroll
    for (int g = 0; g < 4; g++) {
        float x0 = v[4*g+0], x1 = v[4*g+1], x2 = v[4*g+2], x3 = v[4*g+3];
        float s01 = x0 + x1, d01 = x0 - x1;
        float s23 = x2 + x3, d23 = x2 - x3;
        v[4*g+0] = s01 + d23;
        v[4*g+1] = s01 - d23;
        v[4*g+2] = d01 + s23;
        v[4*g+3] = s23 - d01;
    }

    // ---- Stage over b1 (block stride 64): H4 on (b, b+4, b+8, b+12) ----
    #pragma unroll
    for (int g = 0; g < 4; g++) {
        float x0 = v[g+0], x1 = v[g+4], x2 = v[g+8], x3 = v[g+12];
        float s01 = x0 + x1, d01 = x0 - x1;
        float s23 = x2 + x3, d23 = x2 - x3;
        v[g+0]  = s01 + d23;
        v[g+4]  = s01 - d23;
        v[g+8]  = d01 + s23;
        v[g+12] = s23 - d01;
    }

    // ---- Transpose via smem: write W[b][q], read row W[q][*] ----
    #pragma unroll
    for (int b = 0; b < 16; b++)
        W[b * 20 + q] = v[b];

    __syncwarp();

    float u[16];
    {
        const float4* row = reinterpret_cast<const float4*>(W + q * 20u);
        float4 r0 = row[0];
        float4 r1 = row[1];
        float4 r2 = row[2];
        float4 r3 = row[3];
        u[0]=r0.x;  u[1]=r0.y;  u[2]=r0.z;  u[3]=r0.w;
        u[4]=r1.x;  u[5]=r1.y;  u[6]=r1.z;  u[7]=r1.w;
        u[8]=r2.x;  u[9]=r2.y;  u[10]=r2.z; u[11]=r2.w;
        u[12]=r3.x; u[13]=r3.y; u[14]=r3.z; u[15]=r3.w;
    }

    // ---- Stage over a0 (stride 1) ----
    #pragma unroll
    for (int g = 0; g < 4; g++) {
        float x0 = u[4*g+0], x1 = u[4*g+1], x2 = u[4*g+2], x3 = u[4*g+3];
        float s01 = x0 + x1, d01 = x0 - x1;
        float s23 = x2 + x3, d23 = x2 - x3;
        u[4*g+0] = s01 + d23;
        u[4*g+1] = s01 - d23;
        u[4*g+2] = d01 + s23;
        u[4*g+3] = s23 - d01;
    }

    // ---- Stage over a1 (stride 4), fold 1/16 scale ----
    #pragma unroll
    for (int g = 0; g < 4; g++) {
        float x0 = u[g+0], x1 = u[g+4], x2 = u[g+8], x3 = u[g+12];
        float s01 = x0 + x1, d01 = x0 - x1;
        float s23 = x2 + x3, d23 = x2 - x3;
        u[g+0]  = (s01 + d23) * 0.0625f;
        u[g+4]  = (s01 - d23) * 0.0625f;
        u[g+8]  = (d01 + s23) * 0.0625f;
        u[g+12] = (s23 - d01) * 0.0625f;
    }

    // ---- Store: thread q owns y[gbase + 16*q + a], a = 0..15 consecutive ----
    float4* dst = reinterpret_cast<float4*>(out + gbase + (size_t)q * 16u);
    dst[0] = make_float4(u[0],  u[1],  u[2],  u[3]);
    dst[1] = make_float4(u[4],  u[5],  u[6],  u[7]);
    dst[2] = make_float4(u[8],  u[9],  u[10], u[11]);
    dst[3] = make_float4(u[12], u[13], u[14], u[15]);
}

extern "C" void kernel_launch(void* const* d_in, const int* in_sizes, int n_in,
                              void* d_out, int out_size)
{
    const float* x = (const float*)d_in[0];
    float* out = (float*)d_out;

    // out_size = 2*4096*8192 = 67,108,864 floats.
    // One warp handles 512 floats; 8 warps (256 threads) per CTA -> 4096 floats/CTA.
    const long long n = (long long)out_size;
    const int cta_elems = 4096;
    const int grid = (int)(n / cta_elems);   // 16384, exact

    hadamard256_kernel<<<grid, 256>>>(x, out);
}

// round 6
// speedup vs baseline: 1.4309x; 1.1628x over previous
#include <cuda_runtime.h>
#include <cstdint>

// Blocked Hadamard transform, BLOCK = 256 = 4^4.
// H4 = ones(4) - 2*antidiag ; H = kron(H4 x4) / 16.
// In-block index i = i0 + 4*i1 + 16*i2 + 64*i3 (base-4 digits).
//
// Warp handles 512 consecutive floats (2 blocks). Thread layout:
//   v[c] = x[wbase + 32*c + lane],  c = 0..15
// so  lane = i0 + 4*i1 + 16*(i2&1),  c&7 = (i2>>1) + 2*i3,  block = c>>3.
// Every global access (load and store) is a fully-coalesced 128B line.
//
// Stages:
//   i3  : register-local H4 over c-groups {c0, c0+2, c0+4, c0+6}
//   i2  : split digit (lane bit 4, c bit 0): 1 shuffle per value:
//         As=shfl16(A), Bs=shfl16(B); A'=(A+As)+(B-Bs); B'=(A-As)+(B+Bs)
//   i1  : lane bits [3:2], 2-shuffle identity (xor 4, then xor 8 on diff)
//   i0  : lane bits [1:0], 2-shuffle identity (xor 1, then xor 2 on diff)
// Final scale 1/16 folded into the last stage. No shared memory, no syncs.

__global__ void __launch_bounds__(256) hadamard256_kernel(
    const float* __restrict__ x, float* __restrict__ out)
{
    const unsigned warp_global = blockIdx.x * 8u + (threadIdx.x >> 5);
    const unsigned lane = threadIdx.x & 31u;
    const size_t base = (size_t)warp_global * 512u + lane;

    float v[16];
    const float* xp = x + base;
    #pragma unroll
    for (int c = 0; c < 16; c++)
        v[c] = __ldcs(xp + 32 * c);

    // ---- Stage i3 (register-local): groups c = c0 + 2t, c0 in {0,1,8,9} ----
    #pragma unroll
    for (int b = 0; b < 2; b++) {
        #pragma unroll
        for (int lo = 0; lo < 2; lo++) {
            const int c0 = 8 * b + lo;
            float x0 = v[c0], x1 = v[c0 + 2], x2 = v[c0 + 4], x3 = v[c0 + 6];
            float s01 = x0 + x1, d01 = x0 - x1;
            float s23 = x2 + x3, d23 = x2 - x3;
            v[c0]     = s01 + d23;   //  x0+x1+x2-x3
            v[c0 + 2] = s01 - d23;   //  x0+x1-x2+x3
            v[c0 + 4] = d01 + s23;   //  x0-x1+x2+x3
            v[c0 + 6] = s23 - d01;   // -x0+x1+x2+x3
        }
    }

    // ---- Stage i2 (lane bit 4  x  c bit 0): 16 shuffles total ----
    #pragma unroll
    for (int t = 0; t < 8; t++) {
        float A = v[2 * t], B = v[2 * t + 1];
        float As = __shfl_xor_sync(0xffffffffu, A, 16);
        float Bs = __shfl_xor_sync(0xffffffffu, B, 16);
        v[2 * t]     = (A + As) + (B - Bs);
        v[2 * t + 1] = (A - As) + (B + Bs);
    }

    // ---- Stage i1 (lane bits [3:2]): 2 shuffles per value ----
    #pragma unroll
    for (int c = 0; c < 16; c++) {
        float a  = __shfl_xor_sync(0xffffffffu, v[c], 4);
        float s  = v[c] + a;
        float d  = v[c] - a;
        float d2 = __shfl_xor_sync(0xffffffffu, d, 8);
        v[c] = s + d2;
    }

    // ---- Stage i0 (lane bits [1:0]): 2 shuffles per value, fold 1/16 ----
    #pragma unroll
    for (int c = 0; c < 16; c++) {
        float a  = __shfl_xor_sync(0xffffffffu, v[c], 1);
        float s  = v[c] + a;
        float d  = v[c] - a;
        float d2 = __shfl_xor_sync(0xffffffffu, d, 2);
        v[c] = (s + d2) * 0.0625f;
    }

    float* op = out + base;
    #pragma unroll
    for (int c = 0; c < 16; c++)
        __stcs(op + 32 * c, v[c]);
}

extern "C" void kernel_launch(void* const* d_in, const int* in_sizes, int n_in,
                              void* d_out, int out_size)
{
    const float* x = (const float*)d_in[0];
    float* out = (float*)d_out;

    // out_size = 2*4096*8192 = 67,108,864 floats.
    // One warp handles 512 floats; 8 warps (256 threads) per CTA -> 4096 floats/CTA.
    const long long n = (long long)out_size;
    const int cta_elems = 4096;
    const int grid = (int)(n / cta_elems);   // 16384, exact

    hadamard256_kernel<<<grid, 256>>>(x, out);
}